// round 2
// baseline (speedup 1.0000x reference)
#include <cuda_runtime.h>
#include <stdint.h>

// Instant-NGP hash grid encode.
// B=524288 points, D=3, L=16 levels, C=2, H=16, hashed table size 2^19.
// Levels 0..2 dense ((res+1)^3 entries), levels 3..15 hashed (524288 entries).
// out[b, l*2 + c] -> float2 store at linear index b*16 + l.

#define NPOINTS  524288
#define NLEVELS  16
#define NPAIRS   (NPOINTS * NLEVELS)

__constant__ int c_offsets[16] = {
    0, 4913, 40850, 315475,
    839763, 1364051, 1888339, 2412627,
    2936915, 3461203, 3985491, 4509779,
    5034067, 5558355, 6082643, 6606931
};

__global__ __launch_bounds__(256)
void hash_encode_kernel(const float* __restrict__ in,
                        const float2* __restrict__ emb,
                        float2* __restrict__ out)
{
    int tid = blockIdx.x * blockDim.x + threadIdx.x;
    if (tid >= NPAIRS) return;

    int b = tid >> 4;
    int l = tid & 15;

    // map [-1,1) -> [0,1)
    float x = (__ldg(&in[b * 3 + 0]) + 1.0f) * 0.5f;
    float y = (__ldg(&in[b * 3 + 1]) + 1.0f) * 0.5f;
    float z = (__ldg(&in[b * 3 + 2]) + 1.0f) * 0.5f;

    uint32_t res = 16u << l;
    float fres = (float)res;

    float px = x * fres, py = y * fres, pz = z * fres;
    float gx = floorf(px), gy = floorf(py), gz = floorf(pz);
    float fx = px - gx,   fy = py - gy,   fz = pz - gz;
    uint32_t ux = (uint32_t)gx, uy = (uint32_t)gy, uz = (uint32_t)gz;

    uint32_t idx[8];

    if (l >= 3) {
        // hashed: xor of coordinate*prime, table size 2^19
        const uint32_t P1 = 2654435761u;
        const uint32_t P2 = 805459861u;
        uint32_t hx0 = ux;           uint32_t hx1 = ux + 1u;     // prime0 = 1
        uint32_t hy0 = uy * P1;      uint32_t hy1 = hy0 + P1;
        uint32_t hz0 = uz * P2;      uint32_t hz1 = hz0 + P2;
#pragma unroll
        for (int c = 0; c < 8; c++) {
            uint32_t h = ((c & 1) ? hx1 : hx0)
                       ^ ((c & 2) ? hy1 : hy0)
                       ^ ((c & 4) ? hz1 : hz0);
            idx[c] = h & 0x7FFFFu;
        }
    } else {
        // dense: strided index, guaranteed < (res+1)^3 (x < 1 strictly)
        uint32_t r1 = res + 1u;
        uint32_t r2 = r1 * r1;
        uint32_t sy0 = uy * r1;  uint32_t sy1 = sy0 + r1;
        uint32_t sz0 = uz * r2;  uint32_t sz1 = sz0 + r2;
        uint32_t sx1 = ux + 1u;
#pragma unroll
        for (int c = 0; c < 8; c++) {
            idx[c] = ((c & 1) ? sx1 : ux)
                   + ((c & 2) ? sy1 : sy0)
                   + ((c & 4) ? sz1 : sz0);
        }
    }

    int base = c_offsets[l];

    // trilinear weights
    float wx[2] = {1.0f - fx, fx};
    float wy[2] = {1.0f - fy, fy};
    float wz[2] = {1.0f - fz, fz};

    // issue all 8 gathers, then accumulate
    float2 v[8];
#pragma unroll
    for (int c = 0; c < 8; c++)
        v[c] = __ldg(&emb[base + (int)idx[c]]);

    float ax = 0.0f, ay = 0.0f;
#pragma unroll
    for (int c = 0; c < 8; c++) {
        float w = wx[c & 1] * wy[(c >> 1) & 1] * wz[c >> 2];
        ax = fmaf(w, v[c].x, ax);
        ay = fmaf(w, v[c].y, ay);
    }

    out[tid] = make_float2(ax, ay);
}

extern "C" void kernel_launch(void* const* d_in, const int* in_sizes, int n_in,
                              void* d_out, int out_size)
{
    const float*  inputs = (const float*)d_in[0];
    const float2* emb    = (const float2*)d_in[1];
    float2*       out    = (float2*)d_out;

    dim3 block(256);
    dim3 grid((NPAIRS + 255) / 256);
    hash_encode_kernel<<<grid, block>>>(inputs, emb, out);
}

// round 5
// speedup vs baseline: 1.0276x; 1.0276x over previous
#include <cuda_runtime.h>
#include <stdint.h>

// Instant-NGP hash grid encode, pair-load optimized.
// B=524288 points, D=3, L=16 levels, C=2, H=16, hashed table size 2^19.
//
// Strategy: x-adjacent corner pairs share an aligned 16B chunk when the low
// index is even (dense: i1=i0+1; hashed: prime_x=1 so ux even => i1=i0^1).
// Repack the embedding table into a __device__ scratch with even (16B-aligned)
// per-level bases, then load such pairs with one LDG.128 instead of two
// LDG.64 — expected 25% reduction in L1tex wavefronts (the 91.9% SOL binder).

#define NPOINTS  524288
#define NLEVELS  16
#define NPAIRS   (NPOINTS * NLEVELS)

// src (original) level offsets: 0,4913,40850,315475, then +524288 each
// dst (aligned) level offsets: pad levels 0..2 by one entry so every base is even
#define TOTAL_DST 7131222

__device__ __align__(16) float2 g_emb[TOTAL_DST];

__constant__ int c_dst_off[16] = {
    0, 4914, 40852, 315478,
    839766, 1364054, 1888342, 2412630,
    2936918, 3461206, 3985494, 4509782,
    5034070, 5558358, 6082646, 6606934
};

// dst index t maps to src index t - shift(t), where shift = number of pad
// entries before t. Pad slots (4913, 40851, 315477 in dst coords) receive
// values from the next level's first entry — they are never read.
__device__ __forceinline__ int repack_shift(int t) {
    return (t >= 315478) ? 3 : (t >= 40852) ? 2 : (t >= 4914) ? 1 : 0;
}

__global__ __launch_bounds__(256)
void repack_kernel(const float2* __restrict__ src)
{
    int t = (blockIdx.x * blockDim.x + threadIdx.x) * 2;  // TOTAL_DST is even
    if (t >= TOTAL_DST) return;
    float2 a = src[t     - repack_shift(t)];
    float2 b = src[t + 1 - repack_shift(t + 1)];
    *reinterpret_cast<float4*>(&g_emb[t]) = make_float4(a.x, a.y, b.x, b.y);
}

// Load corners (i0, i1). If they share an aligned 16B chunk, one LDG.128.
__device__ __forceinline__ void pair_load(const float2* __restrict__ tab,
                                          uint32_t i0, uint32_t i1,
                                          float2& v0, float2& v1)
{
    if ((i0 ^ i1) == 1u) {
        const float4 q = __ldg(reinterpret_cast<const float4*>(tab + (i0 & ~1u)));
        const float2 lo = make_float2(q.x, q.y);
        const float2 hi = make_float2(q.z, q.w);
        if (i0 & 1u) { v0 = hi; v1 = lo; }
        else         { v0 = lo; v1 = hi; }
    } else {
        v0 = __ldg(tab + i0);
        v1 = __ldg(tab + i1);
    }
}

__global__ __launch_bounds__(256)
void hash_encode_kernel(const float* __restrict__ in,
                        float2* __restrict__ out)
{
    int tid = blockIdx.x * blockDim.x + threadIdx.x;
    if (tid >= NPAIRS) return;

    int b = tid >> 4;
    int l = tid & 15;

    // map [-1,1) -> [0,1)
    float x = (__ldg(&in[b * 3 + 0]) + 1.0f) * 0.5f;
    float y = (__ldg(&in[b * 3 + 1]) + 1.0f) * 0.5f;
    float z = (__ldg(&in[b * 3 + 2]) + 1.0f) * 0.5f;

    uint32_t res = 16u << l;
    float fres = (float)res;

    float px = x * fres, py = y * fres, pz = z * fres;
    float gx = floorf(px), gy = floorf(py), gz = floorf(pz);
    float fx = px - gx,   fy = py - gy,   fz = pz - gz;
    uint32_t ux = (uint32_t)gx, uy = (uint32_t)gy, uz = (uint32_t)gz;

    const float2* __restrict__ tab = g_emb + c_dst_off[l];

    // corner c = xbit | (ybit<<1) | (zbit<<2); pair p = ybit | (zbit<<1)
    // v[2p] = x0 corner, v[2p+1] = x1 corner
    float2 v[8];

    if (l >= 3) {
        // hashed: idx = (ux*1 ^ uy*P1 ^ uz*P2) & (2^19 - 1)
        const uint32_t P1 = 2654435761u;
        const uint32_t P2 = 805459861u;
        uint32_t hx0 = ux;        uint32_t hx1 = ux + 1u;
        uint32_t hy0 = uy * P1;   uint32_t hy1 = hy0 + P1;
        uint32_t hz0 = uz * P2;   uint32_t hz1 = hz0 + P2;
#pragma unroll
        for (int p = 0; p < 4; p++) {
            uint32_t hyz = ((p & 1) ? hy1 : hy0) ^ ((p & 2) ? hz1 : hz0);
            uint32_t i0 = (hx0 ^ hyz) & 0x7FFFFu;
            uint32_t i1 = (hx1 ^ hyz) & 0x7FFFFu;
            pair_load(tab, i0, i1, v[2 * p], v[2 * p + 1]);
        }
    } else {
        // dense: idx = ux + uy*(res+1) + uz*(res+1)^2, provably in range
        uint32_t r1 = res + 1u;
        uint32_t r2 = r1 * r1;
        uint32_t sy0 = uy * r1;  uint32_t sy1 = sy0 + r1;
        uint32_t sz0 = uz * r2;  uint32_t sz1 = sz0 + r2;
#pragma unroll
        for (int p = 0; p < 4; p++) {
            uint32_t s = ((p & 1) ? sy1 : sy0) + ((p & 2) ? sz1 : sz0) + ux;
            pair_load(tab, s, s + 1u, v[2 * p], v[2 * p + 1]);
        }
    }

    // trilinear weights
    float wx[2] = {1.0f - fx, fx};
    float wy[2] = {1.0f - fy, fy};
    float wz[2] = {1.0f - fz, fz};

    float ax = 0.0f, ay = 0.0f;
#pragma unroll
    for (int c = 0; c < 8; c++) {
        float w = wx[c & 1] * wy[(c >> 1) & 1] * wz[c >> 2];
        ax = fmaf(w, v[c].x, ax);
        ay = fmaf(w, v[c].y, ay);
    }

    out[tid] = make_float2(ax, ay);
}

extern "C" void kernel_launch(void* const* d_in, const int* in_sizes, int n_in,
                              void* d_out, int out_size)
{
    const float*  inputs = (const float*)d_in[0];
    const float2* emb    = (const float2*)d_in[1];
    float2*       out    = (float2*)d_out;

    // 1) repack table into even-base (16B-aligned) layout. Idempotent,
    //    deterministic, graph-capturable (plain kernel launch, static scratch).
    {
        int nthreads = TOTAL_DST / 2;
        repack_kernel<<<(nthreads + 255) / 256, 256>>>(emb);
    }

    // 2) gather/interpolate
    hash_encode_kernel<<<(NPAIRS + 255) / 256, 256>>>(inputs, out);
}